// round 17
// baseline (speedup 1.0000x reference)
#include <cuda_runtime.h>
#include <cuda_bf16.h>

// x: [B=16, C=64, H=256, W=256] fp32; conv_w [1,2,7,7]; conv_b [1]
// out = x * sigmoid(conv7x7(concat(mean_c(x), max_c(x))) + b)
//
// SINGLE-PASS fused kernel. Block = 8-row x 256-col slab of one batch.
//  P1: read 14 input rows (+-3 halo) x 64 ch, accumulate per-pixel channel
//      sum/max into smem (coalesced, pixel-stationary).
//  P2: 7x7 conv + bias + sigmoid in smem (register sliding window).
//  P3: re-read inner slab (L1/L2 hot), multiply, stream out.
// Full-width tiles -> no horizontal halo; vertical halo rows shared with
// adjacent co-resident blocks via L2. DRAM = x once + out once = 512 MB.

#define B 16
#define C 64
#define HW 65536           // 256*256
#define HWf4 16384
#define PLANE (C * HW)
#define RO 8               // output rows per tile
#define RI 14              // input rows incl. halo
#define WP 264             // padded smem row width (floats): [0,4) and [260,264) = zero pad
#define NTHR 256
#define NTILE 32           // 256 / RO
#define NBLK (B * NTILE)   // 512

__global__ void __launch_bounds__(NTHR)
k_fused(const float* __restrict__ x,
        const float* __restrict__ cw,
        const float* __restrict__ cb,
        float* __restrict__ out) {
    __shared__ float s_avg[RI][WP];     // 14.8 KB
    __shared__ float s_mx[RI][WP];      // 14.8 KB
    __shared__ float4 s_s[RO][64];      // 8 KB  (sigmoid result)
    __shared__ float s_w[98];
    __shared__ float s_bias;

    const int blk = blockIdx.x;
    const int b   = blk >> 5;           // batch
    const int tr  = blk & 31;           // tile row index
    const int r0  = tr * RO;
    const int tid = threadIdx.x;

    if (tid < 98) s_w[tid] = cw[tid];
    if (tid == 98) s_bias = cb[0];

    // zero the 8 horizontal pad floats per row (cols 0..3 and 260..263)
    for (int i = tid; i < RI * 8; i += NTHR) {
        int ri = i >> 3, j = i & 7;
        int col = (j < 4) ? j : 256 + j;       // 0..3, 260..263
        s_avg[ri][col] = 0.f;
        s_mx[ri][col]  = 0.f;
    }

    const float4* xb = reinterpret_cast<const float4*>(x + (size_t)b * PLANE);

    // ---------------- P1: channel mean+max into smem ----------------
    // slot = (input row ri, f4-col c4); 14*64 = 896 slots.
    for (int slot = tid; slot < RI * 64; slot += NTHR) {
        const int ri = slot >> 6;
        const int c4 = slot & 63;
        const int gr = r0 - 3 + ri;

        float4 sum, mx;
        if (gr >= 0 && gr < 256) {
            const size_t base = (size_t)gr * 64 + c4;      // f4 idx in channel plane
            sum = xb[base];                                 // c = 0 (default cache)
            mx  = sum;
#pragma unroll 8
            for (int c = 1; c < C; c++) {
                float4 v = xb[(size_t)c * HWf4 + base];
                sum.x += v.x; sum.y += v.y; sum.z += v.z; sum.w += v.w;
                mx.x = fmaxf(mx.x, v.x); mx.y = fmaxf(mx.y, v.y);
                mx.z = fmaxf(mx.z, v.z); mx.w = fmaxf(mx.w, v.w);
            }
            const float inv = 1.0f / 64.0f;
            sum.x *= inv; sum.y *= inv; sum.z *= inv; sum.w *= inv;
        } else {
            sum = make_float4(0.f, 0.f, 0.f, 0.f);          // conv zero-pad rows
            mx  = sum;
        }
        *reinterpret_cast<float4*>(&s_avg[ri][4 + c4 * 4]) = sum;
        *reinterpret_cast<float4*>(&s_mx[ri][4 + c4 * 4])  = mx;
    }
    __syncthreads();

    // ---------------- P2: 7x7 conv + bias + sigmoid ----------------
    // 8 rows x 64 f4 = 512 positions; 2 per thread.
    for (int pos = tid; pos < RO * 64; pos += NTHR) {
        const int row = pos >> 6;
        const int c4  = pos & 63;
        const int ow  = c4 * 4;

        float a0 = s_bias, a1 = a0, a2 = a0, a3 = a0;
#pragma unroll
        for (int kh = 0; kh < 7; kh++) {
            const float* ra = &s_avg[row + kh][1 + ow];    // cols ow-3 .. ow+6
            const float* rm = &s_mx[row + kh][1 + ow];
            float v[10];
#pragma unroll
            for (int j = 0; j < 10; j++) v[j] = ra[j];
#pragma unroll
            for (int kw = 0; kw < 7; kw++) {
                float wA = s_w[kh * 7 + kw];
                a0 = fmaf(wA, v[kw],     a0);
                a1 = fmaf(wA, v[kw + 1], a1);
                a2 = fmaf(wA, v[kw + 2], a2);
                a3 = fmaf(wA, v[kw + 3], a3);
            }
#pragma unroll
            for (int j = 0; j < 10; j++) v[j] = rm[j];
#pragma unroll
            for (int kw = 0; kw < 7; kw++) {
                float wM = s_w[49 + kh * 7 + kw];
                a0 = fmaf(wM, v[kw],     a0);
                a1 = fmaf(wM, v[kw + 1], a1);
                a2 = fmaf(wM, v[kw + 2], a2);
                a3 = fmaf(wM, v[kw + 3], a3);
            }
        }
        float4 sg;
        sg.x = 1.0f / (1.0f + __expf(-a0));
        sg.y = 1.0f / (1.0f + __expf(-a1));
        sg.z = 1.0f / (1.0f + __expf(-a2));
        sg.w = 1.0f / (1.0f + __expf(-a3));
        s_s[row][c4] = sg;
    }
    __syncthreads();

    // ---------------- P3: out = x * s (x re-read is L1/L2 hot) ----------------
    float4* ob = reinterpret_cast<float4*>(out + (size_t)b * PLANE);
    for (int pos = tid; pos < RO * 64; pos += NTHR) {
        const int row = pos >> 6;
        const int c4  = pos & 63;
        const float4 s = s_s[row][c4];
        const size_t base = (size_t)(r0 + row) * 64 + c4;

#pragma unroll
        for (int cb0 = 0; cb0 < C; cb0 += 8) {
            float4 v[8];
#pragma unroll
            for (int j = 0; j < 8; j++)
                v[j] = __ldcs(xb + (size_t)(cb0 + j) * HWf4 + base);
#pragma unroll
            for (int j = 0; j < 8; j++) {
                v[j].x *= s.x; v[j].y *= s.y; v[j].z *= s.z; v[j].w *= s.w;
                __stcs(ob + (size_t)(cb0 + j) * HWf4 + base, v[j]);
            }
        }
    }
}

// ---------------------------------------------------------------------------
extern "C" void kernel_launch(void* const* d_in, const int* in_sizes, int n_in,
                              void* d_out, int out_size) {
    const float* x  = (const float*)d_in[0];
    const float* cw = (const float*)d_in[1];
    const float* cb = (const float*)d_in[2];
    float* out = (float*)d_out;

    k_fused<<<NBLK, NTHR>>>(x, cw, cb, out);
}